// round 3
// baseline (speedup 1.0000x reference)
#include <cuda_runtime.h>
#include <cuda_bf16.h>

#define THREADS 256
#define KMAX    8
#define SORTN   2048
#define NWARPS  (THREADS / 32)

// per-image results: [img*2+0]=push, [img*2+1]=pull
__device__ float g_img_pp[64];

__global__ __launch_bounds__(THREADS, 1)
void tagloss_kernel(const float* __restrict__ pred,
                    const int*   __restrict__ gt,
                    const float* __restrict__ prop,
                    int N)
{
    const int img  = blockIdx.x;
    const int t    = threadIdx.x;
    const int lane = t & 31;
    const int w    = t >> 5;

    __shared__ unsigned long long keys[SORTN];     // (scoreBits<<32)|~idx, sorted desc
    __shared__ unsigned char      aliveSm[SORTN];  // alive flags for winner scan
    __shared__ float              warpSums[2][NWARPS][5];
    __shared__ float              initCnt[NWARPS];

    if (N > THREADS * KMAX) return;  // layout supports N <= 2048

    const float*  predI = pred + (size_t)img * N * 4;
    const float*  propI = prop + (size_t)img * N * 5;
    const int*    gtI   = gt   + (size_t)img * N;
    const float4* predV = reinterpret_cast<const float4*>(predI);

    // per-thread element data, fully register-resident. element j = t + k*256
    float x1a[KMAX], y1a[KMAX], x2a[KMAX], y2a[KMAX], sca[KMAX];
    float p0a[KMAX], p1a[KMAX], p2a[KMAX], p3a[KMAX];
    int   gta[KMAX];
    unsigned aliveBits = 0;

    #pragma unroll
    for (int k = 0; k < KMAX; k++) {
        int j = t + (k << 8);           // always < SORTN
        unsigned long long key = 0ull;
        unsigned char av = 0;
        x1a[k]=y1a[k]=x2a[k]=y2a[k]=sca[k]=0.f;
        p0a[k]=p1a[k]=p2a[k]=p3a[k]=0.f; gta[k]=-2147483647;
        if (j < N) {
            const float* pr = propI + (size_t)j * 5;
            float X1=pr[0], Y1=pr[1], X2=pr[2], Y2=pr[3], S=pr[4];
            float4 pv = predV[j];
            int g = gtI[j];
            x1a[k]=X1; y1a[k]=Y1; x2a[k]=X2; y2a[k]=Y2; sca[k]=S;
            p0a[k]=pv.x; p1a[k]=pv.y; p2a[k]=pv.z; p3a[k]=pv.w; gta[k]=g;
            if (g >= 0 && (Y2 - Y1) > 0.0f) { aliveBits |= (1u << k); av = 1; }
            // tie-break: equal score -> smaller index first (matches jnp.argmax)
            key = ((unsigned long long)__float_as_uint(S) << 32)
                | (unsigned long long)(unsigned)(~j);
        }
        aliveSm[j] = av;
        keys[j]    = key;
    }
    __syncthreads();

    // ---- one-time bitonic sort, descending by key (replaces per-step argmax) ----
    for (int k2 = 2; k2 <= SORTN; k2 <<= 1) {
        for (int jj = k2 >> 1; jj > 0; jj >>= 1) {
            #pragma unroll
            for (int r = 0; r < SORTN / THREADS; r++) {
                int idx = t + r * THREADS;
                int ixj = idx ^ jj;
                if (ixj > idx) {
                    unsigned long long a = keys[idx];
                    unsigned long long b = keys[ixj];
                    bool swapIt = ((idx & k2) == 0) ? (a < b) : (a > b);
                    if (swapIt) { keys[idx] = b; keys[ixj] = a; }
                }
            }
            __syncthreads();
        }
    }

    // ---- initial alive count ----
    {
        float cf = (float)__popc(aliveBits);
        #pragma unroll
        for (int off = 16; off; off >>= 1)
            cf += __shfl_xor_sync(0xffffffffu, cf, off);
        if (lane == 0) initCnt[w] = cf;
    }
    __syncthreads();
    int aliveCount = 0;
    #pragma unroll
    for (int ww = 0; ww < NWARPS; ww++) aliveCount += (int)initCnt[ww];

    float totPull = 0.f, totPush = 0.f, pullCnt = 0.f, pushCnt = 0.f;
    int p = 0, par = 0;

    // ---- sequential greedy scan; one __syncthreads per iteration ----
    for (int iter = 0; iter < N && aliveCount >= 2; iter++) {
        // phase A: winner = first alive entry in sorted order (all threads, redundant)
        int i;
        for (;;) {
            unsigned long long kk = keys[p];
            i = (int)~((unsigned)kk);
            if (aliveSm[i]) break;
            p++;
        }
        p++;

        // winner data: broadcast global loads (L1-resident after first pass)
        float4 wp = predV[i];
        const float* wb = propI + (size_t)i * 5;
        float bx1 = wb[0], by1 = wb[1], bx2 = wb[2], by2 = wb[3];
        int   wg  = gtI[i];

        // remove winner from its owner's register mask (rem semantics)
        if ((i & (THREADS - 1)) == t) aliveBits &= ~(1u << (i >> 8));

        float pullA = 0.f, pushA = 0.f, pnA = 0.f, qnA = 0.f, rmA = 0.f;
        #pragma unroll
        for (int k = 0; k < KMAX; k++) {
            bool alive = (aliveBits >> k) & 1u;
            // iou > 0  <=>  strictly positive intersection (exact, no division)
            bool ov = alive
                   && (fminf(x2a[k], bx2) > fmaxf(x1a[k], bx1))
                   && (fminf(y2a[k], by2) > fmaxf(y1a[k], by1));
            float d0 = p0a[k] - wp.x;
            float d1 = p1a[k] - wp.y;
            float d2 = p2a[k] - wp.z;
            float d3 = p3a[k] - wp.w;
            float d  = 0.25f * (d0*d0 + d1*d1 + d2*d2 + d3*d3);
            bool check = d < 0.1f;
            bool same  = (gta[k] == wg);
            if (ov && same && !check) { pullA = fmaf(d, sca[k], pullA); pnA += 1.f; }
            if (ov && !same && check) {
                // exp(-d) for d<0.1 via 3rd-order Taylor, |err|<5e-6
                float t1 = fmaf(d, -0.16666667f, 0.5f);
                float e  = fmaf(d * d, t1, 1.0f - d);
                pushA = fmaf(e, sca[k], pushA); qnA += 1.f;
            }
            if (ov && check) {
                aliveBits &= ~(1u << k);
                rmA += 1.f;
                aliveSm[t + (k << 8)] = 0;   // positions > pos(i): race-free vs phase A
            }
        }

        // warp reduction of 5 quantities
        #pragma unroll
        for (int off = 16; off; off >>= 1) {
            pullA += __shfl_xor_sync(0xffffffffu, pullA, off);
            pushA += __shfl_xor_sync(0xffffffffu, pushA, off);
            pnA   += __shfl_xor_sync(0xffffffffu, pnA,   off);
            qnA   += __shfl_xor_sync(0xffffffffu, qnA,   off);
            rmA   += __shfl_xor_sync(0xffffffffu, rmA,   off);
        }
        if (lane == 0) {
            warpSums[par][w][0] = pullA;
            warpSums[par][w][1] = pushA;
            warpSums[par][w][2] = pnA;
            warpSums[par][w][3] = qnA;
            warpSums[par][w][4] = rmA;
        }
        __syncthreads();   // the ONLY barrier per iteration (warpSums double-buffered)

        // cross-warp finish: lanes 0..4 each own one quantity, then shfl-broadcast
        float v = 0.f;
        if (lane < 5) {
            #pragma unroll
            for (int ww = 0; ww < NWARPS; ww++) v += warpSums[par][ww][lane];
        }
        float PL = __shfl_sync(0xffffffffu, v, 0);
        float PS = __shfl_sync(0xffffffffu, v, 1);
        float PN = __shfl_sync(0xffffffffu, v, 2);
        float QN = __shfl_sync(0xffffffffu, v, 3);
        float RM = __shfl_sync(0xffffffffu, v, 4);

        if (PN > 0.f) { totPull += PL / PN; pullCnt += 1.f; }
        if (QN > 0.f) { totPush += PS / QN; pushCnt += 1.f; }
        aliveCount -= 1 + (int)RM;
        par ^= 1;
    }

    if (t == 0) {
        g_img_pp[img * 2 + 0] = totPush / (pushCnt + 1e-6f);
        g_img_pp[img * 2 + 1] = totPull / (pullCnt + 1e-6f);
    }
}

__global__ void combine_kernel(float* __restrict__ out, int imgs)
{
    float ps = 0.f, pl = 0.f;
    for (int i2 = 0; i2 < imgs; i2++) {
        ps += g_img_pp[2 * i2 + 0];
        pl += g_img_pp[2 * i2 + 1];
    }
    out[0] = ps / (float)imgs;   // push_loss (PUSH_WEIGHT = 1)
    out[1] = pl / (float)imgs;   // pull_loss (PULL_WEIGHT = 1)
}

extern "C" void kernel_launch(void* const* d_in, const int* in_sizes, int n_in,
                              void* d_out, int out_size)
{
    const float* pred = (const float*)d_in[0];   // (IMGS, N, 4) f32
    const int*   gt   = (const int*)  d_in[1];   // (IMGS, N)    i32
    const float* prop = (const float*)d_in[2];   // (IMGS, N, 5) f32
    // d_in[3] = gt_bboxes (IMGS, 20, 4) — unused by the reference math

    int imgs = 4, N = 2000;
    if (n_in >= 4 && in_sizes[3] > 0 && in_sizes[3] % 80 == 0)
        imgs = in_sizes[3] / 80;                 // IMGS*20*4 elements
    if (imgs > 0 && in_sizes[1] % imgs == 0)
        N = in_sizes[1] / imgs;
    if (imgs > 32) imgs = 32;                    // scratch limit

    tagloss_kernel<<<imgs, THREADS>>>(pred, gt, prop, N);
    combine_kernel<<<1, 1>>>((float*)d_out, imgs);
}